// round 7
// baseline (speedup 1.0000x reference)
#include <cuda_runtime.h>
#include <cuda_bf16.h>
#include <math.h>
#include <cstdint>

#define N_      16
#define C_      128
#define T_      16384
#define K_      64
#define KG_     73
#define TT_     64
#define TILES_  (T_ / TT_)   // 256
#define SL_     18           // 16*18 = 288 CTAs = 2/SM
#define EPSF    1e-12f

__device__ float g_vlad_part[SL_ * N_ * K_ * C_];   // 9.4 MB
__device__ float g_asum_part[SL_ * N_ * K_];
__device__ float g_knorm[N_ * K_];

// ---- smem layout (bytes), per CTA ~93 KB -> 2 CTAs/SM ----
#define XS_HI   0        // x hi [c=128][t=64] bf16, 128B rows, swizzled
#define XS_LO   16384
#define W_HI    32768    // W hi [k=80][c=128] bf16, 256B rows (rows 73..79 zero)
#define W_LO    53248
#define SF_HI   73728    // soft hi [t=64][k=64] bf16, 128B rows, swizzled
#define SF_LO   81920
#define NRMP    90112    // float [8][64]
#define MPART   92160    // float [2][64]  local max per (k-half, t)
#define SPART   92672    // float [2][64]  local expsum
#define ASW     93184    // float [8][64]
#define SMEM_SZ 95232

__device__ __forceinline__ void ldsm4(uint32_t a, uint32_t r[4]) {
    asm volatile("ldmatrix.sync.aligned.m8n8.x4.shared.b16 {%0,%1,%2,%3}, [%4];"
        : "=r"(r[0]), "=r"(r[1]), "=r"(r[2]), "=r"(r[3]) : "r"(a));
}
__device__ __forceinline__ void ldsm4t(uint32_t a, uint32_t r[4]) {
    asm volatile("ldmatrix.sync.aligned.m8n8.x4.trans.shared.b16 {%0,%1,%2,%3}, [%4];"
        : "=r"(r[0]), "=r"(r[1]), "=r"(r[2]), "=r"(r[3]) : "r"(a));
}
__device__ __forceinline__ void mma16816(float d[4], const uint32_t a[4], const uint32_t b[2]) {
    asm volatile("mma.sync.aligned.m16n8k16.row.col.f32.bf16.bf16.f32 "
        "{%0,%1,%2,%3}, {%4,%5,%6,%7}, {%8,%9}, {%0,%1,%2,%3};"
        : "+f"(d[0]), "+f"(d[1]), "+f"(d[2]), "+f"(d[3])
        : "r"(a[0]), "r"(a[1]), "r"(a[2]), "r"(a[3]), "r"(b[0]), "r"(b[1]));
}
__device__ __forceinline__ uint32_t ldsm_addr(uint32_t base, int row0, int colb0, int rs, int lane) {
    int g = lane >> 3, r = lane & 7;
    int row  = row0 + r + ((g & 2) << 2);
    int colb = colb0 + ((g & 1) << 4);
    return base + row * rs + (colb ^ ((row & 7) << 4));
}
__device__ __forceinline__ void hilo2(float z0, float z1, uint32_t& hw, uint32_t& lw) {
    uint32_t h;
    asm("cvt.rn.bf16x2.f32 %0, %2, %1;" : "=r"(h) : "f"(z0), "f"(z1));
    float f0 = __uint_as_float(h << 16);
    float f1 = __uint_as_float(h & 0xFFFF0000u);
    uint32_t l;
    asm("cvt.rn.bf16x2.f32 %0, %2, %1;" : "=r"(l) : "f"(z0 - f0), "f"(z1 - f1));
    hw = h; lw = l;
}
__device__ __forceinline__ float2 ffma2(float2 a, float2 b, float2 c) {
    float2 d;
    asm("fma.rn.f32x2 %0, %1, %2, %3;"
        : "=l"(*(unsigned long long*)&d)
        : "l"(*(unsigned long long*)&a),
          "l"(*(unsigned long long*)&b),
          "l"(*(unsigned long long*)&c));
    return d;
}

__global__ __launch_bounds__(256, 2)
void vlad_mma(const float* __restrict__ x, const float* __restrict__ conv_w) {
    extern __shared__ __align__(16) char smem[];
    uint32_t sb;
    asm("{ .reg .u64 t; cvta.to.shared.u64 t, %1; cvt.u32.u64 %0, t; }" : "=r"(sb) : "l"(smem));

    const int n = blockIdx.x, sl = blockIdx.y;
    const int tid = threadIdx.x, w = tid >> 5, lane = tid & 31;
    const int q = lane >> 2, qk = lane & 3;
    const int hl = lane >> 4, lt = lane & 15;

    float* nrmp  = (float*)(smem + NRMP);
    float* mpart = (float*)(smem + MPART);
    float* spart = (float*)(smem + SPART);
    float* asw   = (float*)(smem + ASW);

    // ---- W -> smem hi/lo, swizzled [k=80][c=128], rows >= 73 zero ----
    for (int idx = tid; idx < 80 * 128; idx += 256) {
        int k = idx >> 7, c = idx & 127;
        float v = (k < KG_) ? conv_w[k * 128 + c] : 0.f;
        __nv_bfloat16 h = __float2bfloat16(v);
        __nv_bfloat16 l = __float2bfloat16(v - __bfloat162float(h));
        int phys = k * 256 + ((c * 2) ^ ((k & 7) << 4));
        *(__nv_bfloat16*)(smem + W_HI + phys) = h;
        *(__nv_bfloat16*)(smem + W_LO + phys) = l;
    }
    for (int i = tid; i < 512; i += 256) asw[i] = 0.f;

    // roles
    const int wt1 = w & 3, kh = w >> 2;            // GEMM1: t-block, k-half
    const int npc = kh ? 2 : 3, npb = kh ? 3 : 0;
    const int wk2 = w >> 1, wc = w & 1;            // GEMM2: k-block, c-half
    const int tA = 16 * wt1 + q, tB = tA + 8;

    float acc2[8][4];
#pragma unroll
    for (int i = 0; i < 8; ++i)
#pragma unroll
        for (int j = 0; j < 4; ++j) acc2[i][j] = 0.f;
    float asum_[6][2];
#pragma unroll
    for (int i = 0; i < 6; ++i) { asum_[i][0] = 0.f; asum_[i][1] = 0.f; }

    const float* xb = x + (long)n * C_ * T_;

    for (int tile = sl; tile < TILES_; tile += SL_) {
        __syncthreads();   // B1: XS/SF/nrmp free
        const int t0g = tile * TT_;

        // ---- load (direct LDG, peer CTA hides latency) + convert + norm partials ----
        {
            float4 vv[8];
#pragma unroll
            for (int ci = 0; ci < 8; ++ci) {
                int c = 16 * w + 2 * ci + hl;
                vv[ci] = *(const float4*)(xb + (long)c * T_ + t0g + 4 * lt);
            }
            float2 sqA = make_float2(0.f, 0.f), sqB = make_float2(0.f, 0.f);
#pragma unroll
            for (int ci = 0; ci < 8; ++ci) {
                int c = 16 * w + 2 * ci + hl;
                float4 v = vv[ci];
                float2 p0 = make_float2(v.x, v.y), p1 = make_float2(v.z, v.w);
                sqA = ffma2(p0, p0, sqA);
                sqB = ffma2(p1, p1, sqB);
                uint32_t hw0, lw0, hw1, lw1;
                hilo2(v.x, v.y, hw0, lw0);
                hilo2(v.z, v.w, hw1, lw1);
                int phys = c * 128 + ((8 * lt) ^ ((c & 7) << 4));
                *(uint2*)(smem + XS_HI + phys) = make_uint2(hw0, hw1);
                *(uint2*)(smem + XS_LO + phys) = make_uint2(lw0, lw1);
            }
            // combine hl halves (lane ^ 16)
            sqA.x += __shfl_xor_sync(~0u, sqA.x, 16);
            sqA.y += __shfl_xor_sync(~0u, sqA.y, 16);
            sqB.x += __shfl_xor_sync(~0u, sqB.x, 16);
            sqB.y += __shfl_xor_sync(~0u, sqB.y, 16);
            if (hl == 0)
                *(float4*)(nrmp + w * 64 + 4 * lt) = make_float4(sqA.x, sqA.y, sqB.x, sqB.y);
        }
        __syncthreads();   // B2: XS + nrmp ready

        // ---- GEMM1: logits[t][k-half], warp = (t-block 16, k-half) ----
        float acc1[6][4];
#pragma unroll
        for (int i = 0; i < 6; ++i)
#pragma unroll
            for (int j = 0; j < 4; ++j) acc1[i][j] = 0.f;

#pragma unroll
        for (int kk = 0; kk < 8; ++kk) {
            uint32_t ah[4], al[4];
            ldsm4t(ldsm_addr(sb + XS_HI, 16 * kk, 32 * wt1, 128, lane), ah);
            ldsm4t(ldsm_addr(sb + XS_LO, 16 * kk, 32 * wt1, 128, lane), al);
#pragma unroll
            for (int i = 0; i < 3; ++i) {
                if (i < npc) {
                    int np = npb + i;
                    uint32_t bh[4], bl[4];
                    ldsm4(ldsm_addr(sb + W_HI, 16 * np, 32 * kk, 256, lane), bh);
                    ldsm4(ldsm_addr(sb + W_LO, 16 * np, 32 * kk, 256, lane), bl);
                    mma16816(acc1[2 * i],     ah, bh);
                    mma16816(acc1[2 * i + 1], ah, bh + 2);
                    mma16816(acc1[2 * i],     al, bh);
                    mma16816(acc1[2 * i + 1], al, bh + 2);
                    mma16816(acc1[2 * i],     ah, bl);
                    mma16816(acc1[2 * i + 1], ah, bl + 2);
                }
            }
        }

        // ---- per-thread ninv from nrmp (no extra barrier) ----
        float ssA = 0.f, ssB = 0.f;
#pragma unroll
        for (int ww = 0; ww < 8; ++ww) { ssA += nrmp[ww * 64 + tA]; ssB += nrmp[ww * 64 + tB]; }
        const float ninvA = 1.f / fmaxf(sqrtf(ssA), EPSF);
        const float ninvB = 1.f / fmaxf(sqrtf(ssB), EPSF);

        // ---- softmax: local max + local expsum over this warp's k-half ----
        float mA = -1e30f, mB = -1e30f;
        if (kh == 0) {
#pragma unroll
            for (int nn = 0; nn < 6; ++nn) {
                mA = fmaxf(mA, fmaxf(acc1[nn][0], acc1[nn][1]));
                mB = fmaxf(mB, fmaxf(acc1[nn][2], acc1[nn][3]));
            }
        } else {
#pragma unroll
            for (int nn = 0; nn < 3; ++nn) {
                mA = fmaxf(mA, fmaxf(acc1[nn][0], acc1[nn][1]));
                mB = fmaxf(mB, fmaxf(acc1[nn][2], acc1[nn][3]));
            }
            if (qk == 0) { mA = fmaxf(mA, acc1[3][0]); mB = fmaxf(mB, acc1[3][2]); }
        }
        mA = fmaxf(mA, __shfl_xor_sync(~0u, mA, 1));
        mA = fmaxf(mA, __shfl_xor_sync(~0u, mA, 2));
        mB = fmaxf(mB, __shfl_xor_sync(~0u, mB, 1));
        mB = fmaxf(mB, __shfl_xor_sync(~0u, mB, 2));

        float sA = 0.f, sB = 0.f;
        if (kh == 0) {
#pragma unroll
            for (int nn = 0; nn < 6; ++nn) {
                acc1[nn][0] = __expf((acc1[nn][0] - mA) * ninvA); sA += acc1[nn][0];
                acc1[nn][1] = __expf((acc1[nn][1] - mA) * ninvA); sA += acc1[nn][1];
                acc1[nn][2] = __expf((acc1[nn][2] - mB) * ninvB); sB += acc1[nn][2];
                acc1[nn][3] = __expf((acc1[nn][3] - mB) * ninvB); sB += acc1[nn][3];
            }
        } else {
#pragma unroll
            for (int nn = 0; nn < 3; ++nn) {
                acc1[nn][0] = __expf((acc1[nn][0] - mA) * ninvA); sA += acc1[nn][0];
                acc1[nn][1] = __expf((acc1[nn][1] - mA) * ninvA); sA += acc1[nn][1];
                acc1[nn][2] = __expf((acc1[nn][2] - mB) * ninvB); sB += acc1[nn][2];
                acc1[nn][3] = __expf((acc1[nn][3] - mB) * ninvB); sB += acc1[nn][3];
            }
            if (qk == 0) {
                sA += __expf((acc1[3][0] - mA) * ninvA);
                sB += __expf((acc1[3][2] - mB) * ninvB);
            }
        }
        sA += __shfl_xor_sync(~0u, sA, 1); sA += __shfl_xor_sync(~0u, sA, 2);
        sB += __shfl_xor_sync(~0u, sB, 1); sB += __shfl_xor_sync(~0u, sB, 2);
        if (qk == 0) {
            mpart[kh * 64 + tA] = mA; spart[kh * 64 + tA] = sA;
            mpart[kh * 64 + tB] = mB; spart[kh * 64 + tB] = sB;
        }
        __syncthreads();   // B3: partials exchanged

        // ---- combine halves; rescale factor f = exp((m_local - m)*ninv)/s ----
        float fA, fB;
        {
            float m0 = mpart[tA], m1 = mpart[64 + tA];
            float mg = fmaxf(m0, m1);
            float sg = spart[tA] * __expf((m0 - mg) * ninvA)
                     + spart[64 + tA] * __expf((m1 - mg) * ninvA);
            fA = __expf((mA - mg) * ninvA) / sg;
            m0 = mpart[tB]; m1 = mpart[64 + tB];
            mg = fmaxf(m0, m1);
            sg = spart[tB] * __expf((m0 - mg) * ninvB)
               + spart[64 + tB] * __expf((m1 - mg) * ninvB);
            fB = __expf((mB - mg) * ninvB) / sg;
        }

        // ---- soft -> SF (scaled by ninv), asum accumulate (k<64 only) ----
        {
            const int nstore = kh ? 2 : 6;
            const int swA = (tA & 7) << 4, swB = (tB & 7) << 4;
#pragma unroll
            for (int nn = 0; nn < 6; ++nn) {
                if (nn < nstore) {
                    int k = kh ? (48 + 8 * nn + 2 * qk)
                               : (16 * (nn >> 1) + 8 * (nn & 1) + 2 * qk);
                    float s0 = acc1[nn][0] * fA, s1 = acc1[nn][1] * fA;
                    float s2 = acc1[nn][2] * fB, s3 = acc1[nn][3] * fB;
                    asum_[nn][0] += s0 + s2;
                    asum_[nn][1] += s1 + s3;
                    uint32_t hwA, lwA, hwB, lwB;
                    hilo2(s0 * ninvA, s1 * ninvA, hwA, lwA);
                    hilo2(s2 * ninvB, s3 * ninvB, hwB, lwB);
                    int pA = tA * 128 + ((2 * k) ^ swA);
                    int pB = tB * 128 + ((2 * k) ^ swB);
                    *(uint32_t*)(smem + SF_HI + pA) = hwA;
                    *(uint32_t*)(smem + SF_LO + pA) = lwA;
                    *(uint32_t*)(smem + SF_HI + pB) = hwB;
                    *(uint32_t*)(smem + SF_LO + pB) = lwB;
                }
            }
        }
        __syncthreads();   // B4: SF ready

        // ---- GEMM2: vlad[k][c] += soft_scaled[k][t] x[c][t]; warp = (k16, c64) ----
#pragma unroll
        for (int kk = 0; kk < 4; ++kk) {
            uint32_t ah[4], al[4];
            ldsm4t(ldsm_addr(sb + SF_HI, 16 * kk, 32 * wk2, 128, lane), ah);
            ldsm4t(ldsm_addr(sb + SF_LO, 16 * kk, 32 * wk2, 128, lane), al);
#pragma unroll
            for (int np = 0; np < 4; ++np) {
                uint32_t bh[4], bl[4];
                ldsm4(ldsm_addr(sb + XS_HI, 64 * wc + 16 * np, 32 * kk, 128, lane), bh);
                ldsm4(ldsm_addr(sb + XS_LO, 64 * wc + 16 * np, 32 * kk, 128, lane), bl);
                mma16816(acc2[2 * np],     ah, bh);
                mma16816(acc2[2 * np + 1], ah, bh + 2);
                mma16816(acc2[2 * np],     al, bh);
                mma16816(acc2[2 * np + 1], al, bh + 2);
                mma16816(acc2[2 * np],     ah, bl);
                mma16816(acc2[2 * np + 1], ah, bl + 2);
            }
        }
    }

    // ---- asum: reduce over q (shfl), write own k-slots ----
    __syncthreads();
    {
        const int nstore = kh ? 2 : 6;
#pragma unroll
        for (int nn = 0; nn < 6; ++nn) {
            if (nn < nstore) {
#pragma unroll
                for (int e = 0; e < 2; ++e) {
                    float v = asum_[nn][e];
                    v += __shfl_xor_sync(~0u, v, 4);
                    v += __shfl_xor_sync(~0u, v, 8);
                    v += __shfl_xor_sync(~0u, v, 16);
                    if (lane < 4) {
                        int k = kh ? (48 + 8 * nn + 2 * lane + e)
                                   : (16 * (nn >> 1) + 8 * (nn & 1) + 2 * lane + e);
                        asw[w * 64 + k] = v;
                    }
                }
            }
        }
    }
    __syncthreads();
    if (tid < 64) {
        float s = 0.f;
#pragma unroll
        for (int ww = 0; ww < 8; ++ww) s += asw[ww * 64 + tid];
        g_asum_part[((long)(sl * N_ + n)) * K_ + tid] = s;
    }

    // ---- drain acc2 ----
    {
        const int kA = 16 * wk2 + q, kB = kA + 8;
        float* gp = g_vlad_part + ((long)(sl * N_ + n)) * K_ * C_;
#pragma unroll
        for (int nn = 0; nn < 8; ++nn) {
            int c = 64 * wc + 8 * nn + 2 * qk;
            *(float2*)(gp + (long)kA * C_ + c) = make_float2(acc2[nn][0], acc2[nn][1]);
            *(float2*)(gp + (long)kB * C_ + c) = make_float2(acc2[nn][2], acc2[nn][3]);
        }
    }
}

// ---- Reduce: one CTA per (n,k) ----
__global__ __launch_bounds__(128)
void vlad_reduce(const float* __restrict__ centroids,
                 const float* __restrict__ cwts,
                 float* __restrict__ out) {
    const int k = blockIdx.x, n = blockIdx.y;
    const int tid = threadIdx.x;

    __shared__ float red[128];
    __shared__ float scw;

    float v = 0.f;
    const float* base = g_vlad_part + (long)n * K_ * C_ + (long)k * C_ + tid;
    const long str = (long)N_ * K_ * C_;
#pragma unroll
    for (int sl = 0; sl < SL_; ++sl) v += base[sl * str];

    red[tid] = (tid < SL_) ? g_asum_part[((long)(tid * N_ + n)) * K_ + k] : 0.f;
    if (tid == 0) {
        float s = 0.f;
        for (int kk = 0; kk < K_; ++kk) s += cwts[kk] * cwts[kk];
        scw = 1.f / fmaxf(sqrtf(s), EPSF);
    }
    __syncthreads();
#pragma unroll
    for (int s = 64; s > 0; s >>= 1) { if (tid < s) red[tid] += red[tid + s]; __syncthreads(); }
    const float asumv = red[0];
    __syncthreads();

    v -= asumv * centroids[k * C_ + tid];

    red[tid] = v * v;
    __syncthreads();
#pragma unroll
    for (int s = 64; s > 0; s >>= 1) { if (tid < s) red[tid] += red[tid + s]; __syncthreads(); }
    const float ssq = red[0];

    const float scale = (1.f / fmaxf(sqrtf(ssq), EPSF)) * cwts[k] * scw;
    out[(long)n * K_ * C_ + (long)k * C_ + tid] = v * scale;
    if (tid == 0) g_knorm[n * K_ + k] = ssq * scale * scale;
}

__global__ __launch_bounds__(256)
void vlad_finalize(float* __restrict__ out) {
    const int n = blockIdx.x, tid = threadIdx.x;
    __shared__ float sginv;
    if (tid == 0) {
        float g = 0.f;
        for (int k = 0; k < K_; ++k) g += g_knorm[n * K_ + k];
        sginv = 1.f / fmaxf(sqrtf(g), EPSF);
    }
    __syncthreads();
    const float gi = sginv;
    float4* p = (float4*)(out + (long)n * K_ * C_);
    for (int i = tid; i < (K_ * C_) / 4; i += 256) {
        float4 v = p[i];
        v.x *= gi; v.y *= gi; v.z *= gi; v.w *= gi;
        p[i] = v;
    }
}

extern "C" void kernel_launch(void* const* d_in, const int* in_sizes, int n_in,
                              void* d_out, int out_size) {
    const float* x      = (const float*)d_in[0];
    const float* conv_w = (const float*)d_in[1];
    const float* cent   = (const float*)d_in[2];
    const float* cwts   = (const float*)d_in[3];
    float* out = (float*)d_out;

    cudaFuncSetAttribute(vlad_mma, cudaFuncAttributeMaxDynamicSharedMemorySize, SMEM_SZ);
    vlad_mma<<<dim3(N_, SL_), 256, SMEM_SZ>>>(x, conv_w);
    vlad_reduce<<<dim3(K_, N_), 128>>>(cent, cwts, out);
    vlad_finalize<<<N_, 256>>>(out);
}

// round 8
// speedup vs baseline: 1.5762x; 1.5762x over previous
#include <cuda_runtime.h>
#include <cuda_bf16.h>
#include <math.h>
#include <cstdint>

#define N_      16
#define C_      128
#define T_      16384
#define K_      64
#define KG_     73
#define TT_     128
#define TILES_  (T_ / TT_)   // 128
#define SL_     18           // 16*18 = 288 CTAs = 2/SM, one wave
#define EPSF    1e-12f

__device__ float g_vlad_part[SL_ * N_ * K_ * C_];   // 9.4 MB
__device__ float g_asum_part[SL_ * N_ * K_];
__device__ float g_knorm[N_ * K_];

// ---- smem layout (bytes), ~74 KB -> 2 CTAs/SM ----
#define XS_     0        // x [c=128][t=128] bf16, 256B rows, swizzled
#define W_      32768    // W [k=80][c=128] bf16, 256B rows (rows 73..79 zero)
#define SF_     53248    // soft [t=128][k=64] bf16, 128B rows, swizzled
#define NRMP    69632    // float [8][128]
#define ASW     73728    // float [8][64]
#define SMEM_SZ 75776

__device__ __forceinline__ void ldsm4(uint32_t a, uint32_t r[4]) {
    asm volatile("ldmatrix.sync.aligned.m8n8.x4.shared.b16 {%0,%1,%2,%3}, [%4];"
        : "=r"(r[0]), "=r"(r[1]), "=r"(r[2]), "=r"(r[3]) : "r"(a));
}
__device__ __forceinline__ void ldsm4t(uint32_t a, uint32_t r[4]) {
    asm volatile("ldmatrix.sync.aligned.m8n8.x4.trans.shared.b16 {%0,%1,%2,%3}, [%4];"
        : "=r"(r[0]), "=r"(r[1]), "=r"(r[2]), "=r"(r[3]) : "r"(a));
}
__device__ __forceinline__ void mma16816(float d[4], const uint32_t a[4], const uint32_t b[2]) {
    asm volatile("mma.sync.aligned.m16n8k16.row.col.f32.bf16.bf16.f32 "
        "{%0,%1,%2,%3}, {%4,%5,%6,%7}, {%8,%9}, {%0,%1,%2,%3};"
        : "+f"(d[0]), "+f"(d[1]), "+f"(d[2]), "+f"(d[3])
        : "r"(a[0]), "r"(a[1]), "r"(a[2]), "r"(a[3]), "r"(b[0]), "r"(b[1]));
}
__device__ __forceinline__ uint32_t ldsm_addr(uint32_t base, int row0, int colb0, int rs, int lane) {
    int g = lane >> 3, r = lane & 7;
    int row  = row0 + r + ((g & 2) << 2);
    int colb = colb0 + ((g & 1) << 4);
    return base + row * rs + (colb ^ ((row & 7) << 4));
}
__device__ __forceinline__ uint32_t pack2(float z0, float z1) {
    uint32_t h;
    asm("cvt.rn.bf16x2.f32 %0, %2, %1;" : "=r"(h) : "f"(z0), "f"(z1));
    return h;
}
__device__ __forceinline__ float2 ffma2(float2 a, float2 b, float2 c) {
    float2 d;
    asm("fma.rn.f32x2 %0, %1, %2, %3;"
        : "=l"(*(unsigned long long*)&d)
        : "l"(*(unsigned long long*)&a),
          "l"(*(unsigned long long*)&b),
          "l"(*(unsigned long long*)&c));
    return d;
}

__global__ __launch_bounds__(256, 2)
void vlad_mma(const float* __restrict__ x, const float* __restrict__ conv_w) {
    extern __shared__ __align__(16) char smem[];
    uint32_t sb;
    asm("{ .reg .u64 t; cvta.to.shared.u64 t, %1; cvt.u32.u64 %0, t; }" : "=r"(sb) : "l"(smem));

    const int n = blockIdx.x, sl = blockIdx.y;
    const int tid = threadIdx.x, w = tid >> 5, lane = tid & 31;
    const int q = lane >> 2, qk = lane & 3;

    float* nrmp = (float*)(smem + NRMP);
    float* asw  = (float*)(smem + ASW);

    // ---- W -> smem bf16, swizzled [k=80][c=128], rows >= 73 zero ----
    for (int idx = tid; idx < 80 * 128; idx += 256) {
        int k = idx >> 7, c = idx & 127;
        float v = (k < KG_) ? conv_w[k * 128 + c] : 0.f;
        int phys = k * 256 + ((c * 2) ^ ((k & 7) << 4));
        *(__nv_bfloat16*)(smem + W_ + phys) = __float2bfloat16(v);
    }

    float acc2[8][4];
#pragma unroll
    for (int i = 0; i < 8; ++i)
#pragma unroll
        for (int j = 0; j < 4; ++j) acc2[i][j] = 0.f;
    float asum_[8][2];
#pragma unroll
    for (int i = 0; i < 8; ++i) { asum_[i][0] = 0.f; asum_[i][1] = 0.f; }

    const float* xb = x + (long)n * C_ * T_;
    const int mcol1 = 32 * w;           // GEMM1 A col byte (t-block = 16w)
    const int mcol2 = 32 * (w >> 1);    // GEMM2 A col byte (k-block)
    const int nh2   = 64 * (w & 1);     // GEMM2 c-half
    const int tA    = 16 * w + q, tB = tA + 8;

    for (int tile = sl; tile < TILES_; tile += SL_) {
        __syncthreads();   // B1: XS/SF/nrmp free (prev GEMM1/2 done)
        const int t0g = tile * TT_;

        // ---- load (direct LDG; peer CTA hides latency) + convert + norm partials ----
        {
            float2 sqA = make_float2(0.f, 0.f), sqB = make_float2(0.f, 0.f);
#pragma unroll
            for (int b = 0; b < 2; ++b) {
                float4 vv[8];
#pragma unroll
                for (int ci = 0; ci < 8; ++ci) {
                    int c = 16 * w + 8 * b + ci;
                    vv[ci] = *(const float4*)(xb + (long)c * T_ + t0g + 4 * lane);
                }
#pragma unroll
                for (int ci = 0; ci < 8; ++ci) {
                    int c = 16 * w + 8 * b + ci;
                    float4 v = vv[ci];
                    float2 p0 = make_float2(v.x, v.y), p1 = make_float2(v.z, v.w);
                    sqA = ffma2(p0, p0, sqA);
                    sqB = ffma2(p1, p1, sqB);
                    int phys = c * 256 + ((8 * lane) ^ ((c & 7) << 4));
                    *(uint2*)(smem + XS_ + phys) = make_uint2(pack2(v.x, v.y), pack2(v.z, v.w));
                }
            }
            *(float4*)(nrmp + w * 128 + 4 * lane) = make_float4(sqA.x, sqA.y, sqB.x, sqB.y);
        }
        __syncthreads();   // B2: XS + nrmp ready

        // ---- GEMM1: lg[t][k] (warp owns t 16w..16w+15, all 80 k), single pass ----
        float acc1[10][4];
#pragma unroll
        for (int i = 0; i < 10; ++i)
#pragma unroll
            for (int j = 0; j < 4; ++j) acc1[i][j] = 0.f;

#pragma unroll
        for (int kk = 0; kk < 8; ++kk) {
            uint32_t ah[4];
            ldsm4t(ldsm_addr(sb + XS_, 16 * kk, mcol1, 256, lane), ah);
#pragma unroll
            for (int np = 0; np < 5; ++np) {
                uint32_t bh[4];
                ldsm4(ldsm_addr(sb + W_, 16 * np, 32 * kk, 256, lane), bh);
                mma16816(acc1[2 * np],     ah, bh);
                mma16816(acc1[2 * np + 1], ah, bh + 2);
            }
        }

        // ---- per-thread ninv from nrmp (no extra barrier) ----
        float ssA = 0.f, ssB = 0.f;
#pragma unroll
        for (int ww = 0; ww < 8; ++ww) { ssA += nrmp[ww * 128 + tA]; ssB += nrmp[ww * 128 + tB]; }
        const float ninvA = 1.f / fmaxf(sqrtf(ssA), EPSF);
        const float ninvB = 1.f / fmaxf(sqrtf(ssB), EPSF);

        // ---- softmax (in-register; rows tA, tB); ghosts 64..72 ----
        {
            float mA = -1e30f, mB = -1e30f;
#pragma unroll
            for (int nn = 0; nn < 9; ++nn) {
                mA = fmaxf(mA, fmaxf(acc1[nn][0], acc1[nn][1]));
                mB = fmaxf(mB, fmaxf(acc1[nn][2], acc1[nn][3]));
            }
            if (qk == 0) { mA = fmaxf(mA, acc1[9][0]); mB = fmaxf(mB, acc1[9][2]); }
            mA = fmaxf(mA, __shfl_xor_sync(~0u, mA, 1));
            mA = fmaxf(mA, __shfl_xor_sync(~0u, mA, 2));
            mB = fmaxf(mB, __shfl_xor_sync(~0u, mB, 1));
            mB = fmaxf(mB, __shfl_xor_sync(~0u, mB, 2));

            float sA = 0.f, sB = 0.f;
#pragma unroll
            for (int nn = 0; nn < 9; ++nn) {
                acc1[nn][0] = __expf((acc1[nn][0] - mA) * ninvA); sA += acc1[nn][0];
                acc1[nn][1] = __expf((acc1[nn][1] - mA) * ninvA); sA += acc1[nn][1];
                acc1[nn][2] = __expf((acc1[nn][2] - mB) * ninvB); sB += acc1[nn][2];
                acc1[nn][3] = __expf((acc1[nn][3] - mB) * ninvB); sB += acc1[nn][3];
            }
            if (qk == 0) {
                sA += __expf((acc1[9][0] - mA) * ninvA);
                sB += __expf((acc1[9][2] - mB) * ninvB);
            }
            sA += __shfl_xor_sync(~0u, sA, 1); sA += __shfl_xor_sync(~0u, sA, 2);
            sB += __shfl_xor_sync(~0u, sB, 1); sB += __shfl_xor_sync(~0u, sB, 2);
            const float isA = 1.f / sA, isB = 1.f / sB;

            const int swA = (tA & 7) << 4, swB = (tB & 7) << 4;
#pragma unroll
            for (int nn = 0; nn < 8; ++nn) {
                float s0 = acc1[nn][0] * isA, s1 = acc1[nn][1] * isA;
                float s2 = acc1[nn][2] * isB, s3 = acc1[nn][3] * isB;
                asum_[nn][0] += s0 + s2;
                asum_[nn][1] += s1 + s3;
                int cbyte = 16 * nn + 4 * qk;
                *(uint32_t*)(smem + SF_ + tA * 128 + (cbyte ^ swA)) = pack2(s0 * ninvA, s1 * ninvA);
                *(uint32_t*)(smem + SF_ + tB * 128 + (cbyte ^ swB)) = pack2(s2 * ninvB, s3 * ninvB);
            }
        }
        __syncthreads();   // B3: SF ready

        // ---- GEMM2: vlad[k][c] += soft_scaled[k][t] x[c][t]; warp = (k16, c64) ----
#pragma unroll
        for (int kk = 0; kk < 8; ++kk) {
            uint32_t ah[4];
            ldsm4t(ldsm_addr(sb + SF_, 16 * kk, mcol2, 128, lane), ah);
#pragma unroll
            for (int np = 0; np < 4; ++np) {
                uint32_t bh[4];
                ldsm4(ldsm_addr(sb + XS_, nh2 + 16 * np, 32 * kk, 256, lane), bh);
                mma16816(acc2[2 * np],     ah, bh);
                mma16816(acc2[2 * np + 1], ah, bh + 2);
            }
        }
    }

    // ---- asum reduce ----
    __syncthreads();
#pragma unroll
    for (int nn = 0; nn < 8; ++nn) {
#pragma unroll
        for (int e = 0; e < 2; ++e) {
            float v = asum_[nn][e];
            v += __shfl_xor_sync(~0u, v, 4);
            v += __shfl_xor_sync(~0u, v, 8);
            v += __shfl_xor_sync(~0u, v, 16);
            if (lane < 4) asw[w * 64 + 8 * nn + 2 * lane + e] = v;
        }
    }
    __syncthreads();
    if (tid < 64) {
        float s = 0.f;
#pragma unroll
        for (int ww = 0; ww < 8; ++ww) s += asw[ww * 64 + tid];
        g_asum_part[((long)(sl * N_ + n)) * K_ + tid] = s;
    }

    // ---- drain acc2 ----
    {
        const int kA = 16 * (w >> 1) + q, kB = kA + 8;
        float* gp = g_vlad_part + ((long)(sl * N_ + n)) * K_ * C_;
#pragma unroll
        for (int nn = 0; nn < 8; ++nn) {
            int c = nh2 + 8 * nn + 2 * qk;
            *(float2*)(gp + (long)kA * C_ + c) = make_float2(acc2[nn][0], acc2[nn][1]);
            *(float2*)(gp + (long)kB * C_ + c) = make_float2(acc2[nn][2], acc2[nn][3]);
        }
    }
}

// ---- Reduce: one CTA per (n,k) ----
__global__ __launch_bounds__(128)
void vlad_reduce(const float* __restrict__ centroids,
                 const float* __restrict__ cwts,
                 float* __restrict__ out) {
    const int k = blockIdx.x, n = blockIdx.y;
    const int tid = threadIdx.x;

    __shared__ float red[128];
    __shared__ float scw;

    float v = 0.f;
    const float* base = g_vlad_part + (long)n * K_ * C_ + (long)k * C_ + tid;
    const long str = (long)N_ * K_ * C_;
#pragma unroll
    for (int sl = 0; sl < SL_; ++sl) v += base[sl * str];

    red[tid] = (tid < SL_) ? g_asum_part[((long)(tid * N_ + n)) * K_ + k] : 0.f;
    if (tid == 0) {
        float s = 0.f;
        for (int kk = 0; kk < K_; ++kk) s += cwts[kk] * cwts[kk];
        scw = 1.f / fmaxf(sqrtf(s), EPSF);
    }
    __syncthreads();
#pragma unroll
    for (int s = 64; s > 0; s >>= 1) { if (tid < s) red[tid] += red[tid + s]; __syncthreads(); }
    const float asumv = red[0];
    __syncthreads();

    v -= asumv * centroids[k * C_ + tid];

    red[tid] = v * v;
    __syncthreads();
#pragma unroll
    for (int s = 64; s > 0; s >>= 1) { if (tid < s) red[tid] += red[tid + s]; __syncthreads(); }
    const float ssq = red[0];

    const float scale = (1.f / fmaxf(sqrtf(ssq), EPSF)) * cwts[k] * scw;
    out[(long)n * K_ * C_ + (long)k * C_ + tid] = v * scale;
    if (tid == 0) g_knorm[n * K_ + k] = ssq * scale * scale;
}

__global__ __launch_bounds__(256)
void vlad_finalize(float* __restrict__ out) {
    const int n = blockIdx.x, tid = threadIdx.x;
    __shared__ float sginv;
    if (tid == 0) {
        float g = 0.f;
        for (int k = 0; k < K_; ++k) g += g_knorm[n * K_ + k];
        sginv = 1.f / fmaxf(sqrtf(g), EPSF);
    }
    __syncthreads();
    const float gi = sginv;
    float4* p = (float4*)(out + (long)n * K_ * C_);
    for (int i = tid; i < (K_ * C_) / 4; i += 256) {
        float4 v = p[i];
        v.x *= gi; v.y *= gi; v.z *= gi; v.w *= gi;
        p[i] = v;
    }
}

extern "C" void kernel_launch(void* const* d_in, const int* in_sizes, int n_in,
                              void* d_out, int out_size) {
    const float* x      = (const float*)d_in[0];
    const float* conv_w = (const float*)d_in[1];
    const float* cent   = (const float*)d_in[2];
    const float* cwts   = (const float*)d_in[3];
    float* out = (float*)d_out;

    cudaFuncSetAttribute(vlad_mma, cudaFuncAttributeMaxDynamicSharedMemorySize, SMEM_SZ);
    vlad_mma<<<dim3(N_, SL_), 256, SMEM_SZ>>>(x, conv_w);
    vlad_reduce<<<dim3(K_, N_), 128>>>(cent, cwts, out);
    vlad_finalize<<<N_, 256>>>(out);
}